// round 3
// baseline (speedup 1.0000x reference)
#include <cuda_runtime.h>

#define W_IMG   160
#define H_IMG   160
#define NBITS   128
#define BITS_PB 32           // bits per block (4 groups)
#define TILE_W  168          // padded row stride in words (166 used)
#define TILE_COLS 166
#define R_ROWS  8            // output rows per thread
#define TILE_ROWS (R_ROWS + 5)   // 13: y1 in [0,5], +1 for bilinear
#define PADIMG  3

// grid: 32 (n) * 20 (row-groups of 8) * 4 (bit quarters) = 2560 blocks, 160 threads
__global__ __launch_bounds__(160, 8)
void fern_kernel(const float* __restrict__ x,
                 const float* __restrict__ dx1, const float* __restrict__ dx2,
                 const float* __restrict__ dy1, const float* __restrict__ dy2,
                 const float* __restrict__ th,
                 float* __restrict__ out)
{
    __shared__ float  tile[TILE_ROWS * TILE_W];
    __shared__ float4 sA[BITS_PB];   // vA0, vA1, hA0, hA1
    __shared__ float4 sB[BITS_PB];   // vB0, vB1, hB0, hB1
    __shared__ float  sc0[BITS_PB];
    __shared__ int    soffA[BITS_PB];
    __shared__ int    soffB[BITS_PB];

    const int t    = threadIdx.x;       // 0..159
    const int lane = t & 31;
    const int bx   = blockIdx.x;        // 0..2559
    const int n    = bx / 80;
    const int rem  = bx - n * 80;
    const int hgrp = rem >> 2;
    const int h0   = hgrp * R_ROWS;
    const int bit0 = (rem & 3) * BITS_PB;

    // ---- per-block param precompute, entirely within warp 0 ----
    if (t < 32) {
        // L = max over all 128 entries of |dx1|,|dx2|,|dy1|,|dy2|
        float m = 0.f;
        #pragma unroll
        for (int k = 0; k < 4; k++) {
            int i = t + 32 * k;
            m = fmaxf(m, fabsf(dx1[i]));
            m = fmaxf(m, fabsf(dx2[i]));
            m = fmaxf(m, fabsf(dy1[i]));
            m = fmaxf(m, fabsf(dy2[i]));
        }
        #pragma unroll
        for (int s = 16; s > 0; s >>= 1)
            m = fmaxf(m, __shfl_xor_sync(0xffffffffu, m, s));
        const float L = m;

        const int b = bit0 + t;
        int p = (int)ceilf(L);
        int shift = PADIMG - p;
        float dxa = dx1[b], dya = dy1[b];
        float dxb = dx2[b], dyb = dy2[b];
        float fla = floorf(dxa), flya = floorf(dya);
        float flb = floorf(dxb), flyb = floorf(dyb);
        float fxa = dxa - fla,  fya = dya - flya;
        float fxb = dxb - flb,  fyb = dyb - flyb;
        // int32 cast truncates toward zero, like jnp astype(int32)
        int x1a = (int)(L + fla)  + shift;
        int y1a = (int)(L + flya) + shift;
        int x1b = (int)(L + flb)  + shift;
        int y1b = (int)(L + flyb) + shift;
        // jax.lax.dynamic_slice clamps start to [0, padded - slice] = [0, 5]
        x1a = min(max(x1a, 0), 5);  y1a = min(max(y1a, 0), 5);
        x1b = min(max(x1b, 0), 5);  y1b = min(max(y1b, 0), 5);

        float4 pa, pb;
        pa.x =  0.25f * (1.f - fya);   // vA0
        pa.y =  0.25f * fya;           // vA1
        pa.z =  1.f - fxa;             // hA0
        pa.w =  fxa;                   // hA1
        pb.x = -0.25f * (1.f - fyb);
        pb.y = -0.25f * fyb;
        pb.z =  1.f - fxb;
        pb.w =  fxb;
        sA[t] = pa;  sB[t] = pb;
        sc0[t]   = 0.125f - 0.25f * th[b];
        soffA[t] = y1a * TILE_W + x1a;
        soffB[t] = y1b * TILE_W + x1b;
    }

    // ---- zero-padded input tile (channel 1 only) ----
    const float* ch = x + ((size_t)n * 3 + 1) * (size_t)(H_IMG * W_IMG);
    for (int i = t; i < TILE_ROWS * TILE_COLS; i += 160) {
        int rr = i / TILE_COLS;
        int cc = i - rr * TILE_COLS;
        int gr = h0 + rr - PADIMG;
        int gc = cc - PADIMG;
        float v = 0.f;
        if ((unsigned)gr < (unsigned)H_IMG && (unsigned)gc < (unsigned)W_IMG)
            v = __ldg(ch + gr * W_IMG + gc);
        tile[rr * TILE_W + cc] = v;
    }
    __syncthreads();

    const int w = t;   // lane -> column: conflict-free LDS, coalesced 128B STG
    float* o = out + ((size_t)n * NBITS + bit0) * (size_t)(H_IMG * W_IMG)
                   + (size_t)h0 * W_IMG + w;
    const bool edge = (lane == 31);

    #pragma unroll 1
    for (int bi = 0; bi < BITS_PB; bi++) {
        const float4 pa = sA[bi];
        const float4 pb = sB[bi];
        const float  c0 = sc0[bi];
        const float* baseA = tile + soffA[bi] + w;
        const float* baseB = tile + soffB[bi] + w;

        float tA0 = baseA[0];
        float tB0 = baseB[0];
        float eA0 = 0.f, eB0 = 0.f;
        if (edge) { eA0 = baseA[1]; eB0 = baseB[1]; }

        #pragma unroll
        for (int r = 0; r < R_ROWS; r++) {
            float tA1 = baseA[(r + 1) * TILE_W];
            float tB1 = baseB[(r + 1) * TILE_W];
            float colA = fmaf(pa.y, tA1, pa.x * tA0);
            float colB = fmaf(pb.y, tB1, pb.x * tB0);
            float rA = __shfl_down_sync(0xffffffffu, colA, 1);
            float rB = __shfl_down_sync(0xffffffffu, colB, 1);
            if (edge) {
                float eA1 = baseA[(r + 1) * TILE_W + 1];
                float eB1 = baseB[(r + 1) * TILE_W + 1];
                rA = fmaf(pa.y, eA1, pa.x * eA0);
                rB = fmaf(pb.y, eB1, pb.x * eB0);
                eA0 = eA1; eB0 = eB1;
            }
            float v = c0;
            v = fmaf(pa.z, colA, v);
            v = fmaf(pa.w, rA,  v);
            v = fmaf(pb.z, colB, v);
            v = fmaf(pb.w, rB,  v);
            o[(size_t)r * W_IMG] = __saturatef(v);
            tA0 = tA1; tB0 = tB1;
        }
        o += (size_t)H_IMG * W_IMG;
    }
}

extern "C" void kernel_launch(void* const* d_in, const int* in_sizes, int n_in,
                              void* d_out, int out_size)
{
    const float* x   = (const float*)d_in[0];
    const float* dx1 = (const float*)d_in[1];
    const float* dx2 = (const float*)d_in[2];
    const float* dy1 = (const float*)d_in[3];
    const float* dy2 = (const float*)d_in[4];
    const float* th  = (const float*)d_in[5];
    float* out = (float*)d_out;

    dim3 grid(32 * 20 * 4);
    dim3 block(160);
    fern_kernel<<<grid, block>>>(x, dx1, dx2, dy1, dy2, th, out);
}

// round 4
// speedup vs baseline: 1.2030x; 1.2030x over previous
#include <cuda_runtime.h>

#define W_IMG   160
#define H_IMG   160
#define NBITS   128
#define TILE_W  168          // padded row stride in words (166 used)
#define TILE_COLS 166
#define R_ROWS  8            // output rows per thread
#define TILE_ROWS (R_ROWS + 5)   // 13: y1 in [0,5], +1 for bilinear
#define PADIMG  3

// grid: 32 (n) * 20 (row-groups of 8) * 2 (bit halves) = 1280 blocks, 160 threads
__global__ __launch_bounds__(160, 8)
void fern_kernel(const float* __restrict__ x,
                 const float* __restrict__ dx1, const float* __restrict__ dx2,
                 const float* __restrict__ dy1, const float* __restrict__ dy2,
                 const float* __restrict__ th,
                 float* __restrict__ out)
{
    __shared__ float  tile[TILE_ROWS * TILE_W];
    __shared__ float4 swa[NBITS / 2];
    __shared__ float4 swb[NBITS / 2];
    __shared__ float  sc0[NBITS / 2];
    __shared__ int    soffA[NBITS / 2];
    __shared__ int    soffB[NBITS / 2];

    const int t   = threadIdx.x;        // 0..159
    const int bx  = blockIdx.x;         // 0..1279
    const int n   = bx / 40;
    const int rem = bx - n * 40;
    const int h0  = (rem >> 1) * R_ROWS;
    const int bit0 = (rem & 1) * (NBITS / 2);

    // ---- per-block param precompute: warps 0+1 handle 64 bits, warp-local L ----
    if (t < 64) {
        const int lane = t & 31;
        // L = max over all 128 entries of |dx1|,|dx2|,|dy1|,|dy2| (warp reduction)
        float m = 0.f;
        #pragma unroll
        for (int k = 0; k < 4; k++) {
            int i = lane + 32 * k;
            m = fmaxf(m, fabsf(dx1[i]));
            m = fmaxf(m, fabsf(dx2[i]));
            m = fmaxf(m, fabsf(dy1[i]));
            m = fmaxf(m, fabsf(dy2[i]));
        }
        #pragma unroll
        for (int s = 16; s > 0; s >>= 1)
            m = fmaxf(m, __shfl_xor_sync(0xffffffffu, m, s));
        const float L = m;

        const int b = bit0 + t;
        int p = (int)ceilf(L);
        int shift = PADIMG - p;
        float dxa = dx1[b], dya = dy1[b];
        float dxb = dx2[b], dyb = dy2[b];
        float fla = floorf(dxa), flya = floorf(dya);
        float flb = floorf(dxb), flyb = floorf(dyb);
        float fxa = dxa - fla,  fya = dya - flya;
        float fxb = dxb - flb,  fyb = dyb - flyb;
        // int32 cast truncates toward zero, like jnp astype(int32)
        int x1a = (int)(L + fla)  + shift;
        int y1a = (int)(L + flya) + shift;
        int x1b = (int)(L + flb)  + shift;
        int y1b = (int)(L + flyb) + shift;
        // jax.lax.dynamic_slice clamps start to [0, padded - slice] = [0, 5]
        x1a = min(max(x1a, 0), 5);  y1a = min(max(y1a, 0), 5);
        x1b = min(max(x1b, 0), 5);  y1b = min(max(y1b, 0), 5);

        float4 wa, wb;
        wa.x =  0.25f * (1.f - fxa) * (1.f - fya);
        wa.y =  0.25f * fxa         * (1.f - fya);
        wa.z =  0.25f * (1.f - fxa) * fya;
        wa.w =  0.25f * fxa         * fya;
        wb.x = -0.25f * (1.f - fxb) * (1.f - fyb);
        wb.y = -0.25f * fxb         * (1.f - fyb);
        wb.z = -0.25f * (1.f - fxb) * fyb;
        wb.w = -0.25f * fxb         * fyb;
        swa[t] = wa;  swb[t] = wb;
        sc0[t]   = 0.125f - 0.25f * th[b];
        soffA[t] = y1a * TILE_W + x1a;
        soffB[t] = y1b * TILE_W + x1b;
    }

    // ---- zero-padded input tile (channel 1 only) ----
    const float* ch = x + ((size_t)n * 3 + 1) * (size_t)(H_IMG * W_IMG);
    for (int i = t; i < TILE_ROWS * TILE_COLS; i += 160) {
        int rr = i / TILE_COLS;
        int cc = i - rr * TILE_COLS;
        int gr = h0 + rr - PADIMG;
        int gc = cc - PADIMG;
        float v = 0.f;
        if ((unsigned)gr < (unsigned)H_IMG && (unsigned)gc < (unsigned)W_IMG)
            v = __ldg(ch + gr * W_IMG + gc);
        tile[rr * TILE_W + cc] = v;
    }
    __syncthreads();

    const int w = t;   // lanes consecutive -> conflict-free LDS, coalesced 128B STG
    float* o = out + ((size_t)n * NBITS + bit0) * (size_t)(H_IMG * W_IMG)
                   + (size_t)h0 * W_IMG + w;

    #pragma unroll 1
    for (int bi = 0; bi < NBITS / 2; bi++) {
        const float4 wa = swa[bi];
        const float4 wb = swb[bi];
        const float  c0 = sc0[bi];
        const float* pa = tile + soffA[bi] + w;
        const float* pb = tile + soffB[bi] + w;

        float a0 = pa[0], a1 = pa[1];
        float b0 = pb[0], b1 = pb[1];
        #pragma unroll
        for (int r = 0; r < R_ROWS; r++) {
            float a2 = pa[(r + 1) * TILE_W];
            float a3 = pa[(r + 1) * TILE_W + 1];
            float b2 = pb[(r + 1) * TILE_W];
            float b3 = pb[(r + 1) * TILE_W + 1];
            float v = fmaf(wa.x, a0, c0);
            v = fmaf(wa.y, a1, v);
            v = fmaf(wa.z, a2, v);
            v = fmaf(wa.w, a3, v);
            v = fmaf(wb.x, b0, v);
            v = fmaf(wb.y, b1, v);
            v = fmaf(wb.z, b2, v);
            v = fmaf(wb.w, b3, v);
            o[(size_t)r * W_IMG] = __saturatef(v);
            a0 = a2; a1 = a3; b0 = b2; b1 = b3;
        }
        o += (size_t)H_IMG * W_IMG;
    }
}

extern "C" void kernel_launch(void* const* d_in, const int* in_sizes, int n_in,
                              void* d_out, int out_size)
{
    const float* x   = (const float*)d_in[0];
    const float* dx1 = (const float*)d_in[1];
    const float* dx2 = (const float*)d_in[2];
    const float* dy1 = (const float*)d_in[3];
    const float* dy2 = (const float*)d_in[4];
    const float* th  = (const float*)d_in[5];
    float* out = (float*)d_out;

    dim3 grid(32 * 20 * 2);
    dim3 block(160);
    fern_kernel<<<grid, block>>>(x, dx1, dx2, dy1, dy2, th, out);
}